// round 8
// baseline (speedup 1.0000x reference)
#include <cuda_runtime.h>
#include <cuda_fp16.h>

// Problem constants
#define N_   8
#define C_   64
#define H_   256
#define W_   256
#define HO_  256
#define WO_  256
#define HW_  (H_ * W_)

#define NBLK 740          // 148 SMs x 5 blocks — guaranteed co-resident

// NHWC fp16 scratch (67 MB). Written by T-stage, read by S-stage one stage
// later -> hot in L2. No allocation.
__device__ __half g_xt[(size_t)N_ * HW_ * C_];

// Grid-barrier state (sense-reversing; epoch monotonically increases across
// graph replays, equality-compare handles wrap).
__device__ unsigned g_bar_cnt = 0;
__device__ volatile unsigned g_bar_epoch = 0;

static __device__ __forceinline__ unsigned int h2_as_u(__half2 h) {
    return *reinterpret_cast<unsigned int*>(&h);
}

// Shared-memory union: T staging and S staging alias (never live together).
union SmemU {
    unsigned int smw[64 * 64];            // T: [ch][pixpair] 16 KB
    struct {
        int4         soff[64];            // S: corner offsets (half2 units)
        float4       sw[64];              // S: bilinear weights
        unsigned int smq[64 * 33];        // S: half2 result staging
    } s;
};

// -------------------------------------------------------------------------
// Software grid barrier: all NBLK blocks are co-resident by construction.
// -------------------------------------------------------------------------
static __device__ __forceinline__ void grid_barrier() {
    __syncthreads();
    if (threadIdx.x == 0) {
        __threadfence();                       // publish this block's writes
        const unsigned e = g_bar_epoch;
        if (atomicAdd(&g_bar_cnt, 1u) == NBLK - 1u) {
            g_bar_cnt = 0u;
            __threadfence();
            g_bar_epoch = e + 1u;              // release
        } else {
            while (g_bar_epoch == e) { __nanosleep(64); }
        }
    }
    __syncthreads();
}

// -------------------------------------------------------------------------
// T-chunk: 128 pixels x 64 channels of image n, NCHW fp32 -> NHWC fp16.
// (R6 transpose body, as a device function.)
// -------------------------------------------------------------------------
static __device__ void t_chunk(const float* __restrict__ x, int n, int tb,
                               SmemU* u, int tid) {
    __syncthreads();                           // smem reuse guard
    const int s0  = tb * 128;
    const float* xin = x + (size_t)n * (C_ * HW_);
    const int lane = tid & 31;
    const int cb   = tid >> 5;                 // 0..7

    #pragma unroll
    for (int i = 0; i < 8; i++) {
        const int c = i * 8 + cb;
        const float4 v = __ldcs((const float4*)(xin + (size_t)c * HW_ + s0) + lane);
        const unsigned int u0 = h2_as_u(__floats2half2_rn(v.x, v.y));
        const unsigned int u1 = h2_as_u(__floats2half2_rn(v.z, v.w));
        const int w0 = c * 64 + lane * 2;
        const int ws = w0 ^ (((c >> 3) & 7) << 2);
        *(uint2*)&u->smw[ws] = make_uint2(u0, u1);
    }
    __syncthreads();

    uint4* ob = (uint4*)(g_xt + ((size_t)n * HW_ + s0) * C_);
    #pragma unroll
    for (int j = 0; j < 2; j++) {
        const int uu = tid + 256 * j;          // 0..511
        const int p2 = (uu >> 3) * 2;          // even pixel 0..126
        const int c8 = uu & 7;
        const int c0 = c8 * 8;
        const int sw = c8 << 2;

        unsigned int w8[8];
        #pragma unroll
        for (int jj = 0; jj < 8; jj++) {
            const int w = (c0 + jj) * 64 + (p2 >> 1);
            w8[jj] = u->smw[w ^ sw];
        }
        uint4 lo, hi;
        lo.x = __byte_perm(w8[0], w8[1], 0x5410);
        lo.y = __byte_perm(w8[2], w8[3], 0x5410);
        lo.z = __byte_perm(w8[4], w8[5], 0x5410);
        lo.w = __byte_perm(w8[6], w8[7], 0x5410);
        hi.x = __byte_perm(w8[0], w8[1], 0x7632);
        hi.y = __byte_perm(w8[2], w8[3], 0x7632);
        hi.z = __byte_perm(w8[4], w8[5], 0x7632);
        hi.w = __byte_perm(w8[6], w8[7], 0x7632);

        ob[p2 * 8 + c8]       = lo;
        ob[(p2 + 1) * 8 + c8] = hi;
    }
}

// -------------------------------------------------------------------------
// S-chunk: 64 output pixels of one (n, ho) row. (R7 sample body.)
// -------------------------------------------------------------------------
static __device__ void s_chunk(const float* __restrict__ grid,
                               float* __restrict__ out,
                               int n, int sb, SmemU* u, int tid) {
    __syncthreads();                           // smem reuse guard
    const int wo_base = (sb & 3) * 64;
    const int ho      = sb >> 2;
    const int warp = tid >> 5;
    const int lane = tid & 31;

    if (tid < 64) {
        const float2* gp =
            (const float2*)(grid + (((size_t)n * HO_ + ho) * WO_ + wo_base) * 2);
        const float2 g = __ldcs(&gp[tid]);

        const float ix = (g.x + 1.0f) * 0.5f * (float)(W_ - 1);
        const float iy = (g.y + 1.0f) * 0.5f * (float)(H_ - 1);

        const float x0f = floorf(ix);
        const float y0f = floorf(iy);
        const float wx1 = ix - x0f;
        const float wy1 = iy - y0f;
        const float wx0 = 1.0f - wx1;
        const float wy0 = 1.0f - wy1;

        const int xi = (int)x0f;
        const int yi = (int)y0f;
        const int x0 = min(max(xi,     0), W_ - 1);
        const int x1 = min(max(xi + 1, 0), W_ - 1);
        const int y0 = min(max(yi,     0), H_ - 1);
        const int y1 = min(max(yi + 1, 0), H_ - 1);

        int4 o;                                // offsets in half2 units
        o.x = (y0 * W_ + x0) * (C_ / 2);
        o.y = (y0 * W_ + x1) * (C_ / 2);
        o.z = (y1 * W_ + x0) * (C_ / 2);
        o.w = (y1 * W_ + x1) * (C_ / 2);
        u->s.soff[tid] = o;
        u->s.sw[tid] = make_float4(wy0 * wx0, wy0 * wx1, wy1 * wx0, wy1 * wx1);
    }
    __syncthreads();

    const __half2* xt2 = (const __half2*)(g_xt + (size_t)n * ((size_t)HW_ * C_));

    #pragma unroll
    for (int i = 0; i < 8; i += 4) {
        int4    o[4];
        float4  w[4];
        __half2 v[4][4];

        #pragma unroll
        for (int j = 0; j < 4; j++) {
            const int p = warp * 8 + i + j;
            o[j] = u->s.soff[p];
            w[j] = u->s.sw[p];
        }
        #pragma unroll
        for (int j = 0; j < 4; j++) {          // 16 gathers in flight
            v[j][0] = xt2[o[j].x + lane];
            v[j][1] = xt2[o[j].y + lane];
            v[j][2] = xt2[o[j].z + lane];
            v[j][3] = xt2[o[j].w + lane];
        }
        #pragma unroll
        for (int j = 0; j < 4; j++) {
            const float2 f00 = __half22float2(v[j][0]);
            const float2 f01 = __half22float2(v[j][1]);
            const float2 f10 = __half22float2(v[j][2]);
            const float2 f11 = __half22float2(v[j][3]);
            float rx = w[j].x * f00.x, ry = w[j].x * f00.y;
            rx = fmaf(w[j].y, f01.x, rx);  ry = fmaf(w[j].y, f01.y, ry);
            rx = fmaf(w[j].z, f10.x, rx);  ry = fmaf(w[j].z, f10.y, ry);
            rx = fmaf(w[j].w, f11.x, rx);  ry = fmaf(w[j].w, f11.y, ry);
            u->s.smq[(warp * 8 + i + j) * 33 + lane] =
                h2_as_u(__floats2half2_rn(rx, ry));
        }
    }
    __syncthreads();

    float* obase = out + (size_t)n * (C_ * HO_ * WO_) + (size_t)ho * WO_ + wo_base;
    #pragma unroll
    for (int it = 0; it < 4; it++) {
        const int uu = tid + 256 * it;         // 0..1023
        const int c  = uu >> 4;                // channel 0..63
        const int q  = uu & 15;                // float4 chunk within 64 pixels
        const int cp = c >> 1;
        const int hi = c & 1;

        float4 vv;
        {
            const __half2 h0 = *(const __half2*)&u->s.smq[(q * 4 + 0) * 33 + cp];
            const __half2 h1 = *(const __half2*)&u->s.smq[(q * 4 + 1) * 33 + cp];
            const __half2 h2 = *(const __half2*)&u->s.smq[(q * 4 + 2) * 33 + cp];
            const __half2 h3 = *(const __half2*)&u->s.smq[(q * 4 + 3) * 33 + cp];
            vv.x = hi ? __high2float(h0) : __low2float(h0);
            vv.y = hi ? __high2float(h1) : __low2float(h1);
            vv.z = hi ? __high2float(h2) : __low2float(h2);
            vv.w = hi ? __high2float(h3) : __low2float(h3);
        }
        __stcs((float4*)(obase + (size_t)c * (HO_ * WO_) + q * 4), vv);
    }
}

// -------------------------------------------------------------------------
// Fused persistent kernel: 9 stages. Stage k: transpose image k (if k<8)
// concurrently with sampling image k-1 (if k>0). Grid barrier between
// stages orders T(k) before S(k).
// -------------------------------------------------------------------------
__global__ __launch_bounds__(256, 5) void fused_kernel(
    const float* __restrict__ x, const float* __restrict__ grid,
    float* __restrict__ out) {
    __shared__ SmemU u;
    const int bid = blockIdx.x;
    const int tid = threadIdx.x;

    #pragma unroll 1
    for (int stage = 0; stage < N_ + 1; stage++) {
        if (stage < N_) {
            for (int tb = bid; tb < 512; tb += NBLK)
                t_chunk(x, stage, tb, &u, tid);
        }
        if (stage > 0) {
            for (int sb = bid; sb < 1024; sb += NBLK)
                s_chunk(grid, out, stage - 1, sb, &u, tid);
        }
        if (stage < N_) grid_barrier();
    }
}

extern "C" void kernel_launch(void* const* d_in, const int* in_sizes, int n_in,
                              void* d_out, int out_size) {
    const float* x    = (const float*)d_in[0];   // [N, C, H, W]
    const float* grid = (const float*)d_in[1];   // [N, HO, WO, 2]
    float* out        = (float*)d_out;           // [N, C, HO, WO]
    (void)in_sizes; (void)n_in; (void)out_size;

    fused_kernel<<<NBLK, 256>>>(x, grid, out);
}

// round 9
// speedup vs baseline: 1.9081x; 1.9081x over previous
#include <cuda_runtime.h>
#include <cuda_fp16.h>

// Problem constants
#define N_   8
#define C_   64
#define H_   256
#define W_   256
#define HO_  256
#define WO_  256
#define HW_  (H_ * W_)

// NHWC fp16 scratch for all images (67 MB, mostly L2-resident thanks to
// streaming hints on x/out). No allocation.
__device__ __half g_xt[(size_t)N_ * HW_ * C_];

static __device__ __forceinline__ unsigned int h2_as_u(__half2 h) {
    return *reinterpret_cast<unsigned int*>(&h);
}
static __device__ __forceinline__ __half2 u_as_h2(unsigned int u) {
    return *reinterpret_cast<__half2*>(&u);
}

// -------------------------------------------------------------------------
// Kernel 1: NCHW fp32 -> NHWC fp16. (R6 body — proven)
// -------------------------------------------------------------------------
__global__ __launch_bounds__(256) void nchw_to_nhwc_h(const float* __restrict__ x) {
    __shared__ unsigned int smw[64 * 64];   // [ch][pixpair] 16KB

    const int n   = blockIdx.y;
    const int s0  = blockIdx.x * 128;
    const float* xin = x + (size_t)n * (C_ * HW_);
    const int tid  = threadIdx.x;
    const int lane = tid & 31;
    const int cb   = tid >> 5;              // 0..7

    #pragma unroll
    for (int i = 0; i < 8; i++) {
        const int c = i * 8 + cb;
        const float4 v = __ldcs((const float4*)(xin + (size_t)c * HW_ + s0) + lane);
        const unsigned int u0 = h2_as_u(__floats2half2_rn(v.x, v.y));
        const unsigned int u1 = h2_as_u(__floats2half2_rn(v.z, v.w));
        const int w0 = c * 64 + lane * 2;
        const int ws = w0 ^ (((c >> 3) & 7) << 2);   // keeps 8B alignment
        *(uint2*)&smw[ws] = make_uint2(u0, u1);
    }
    __syncthreads();

    uint4* ob = (uint4*)(g_xt + ((size_t)n * HW_ + s0) * C_);
    #pragma unroll
    for (int j = 0; j < 2; j++) {
        const int u  = tid + 256 * j;       // 0..511
        const int p2 = (u >> 3) * 2;        // even pixel 0..126
        const int c8 = u & 7;               // channel-octet index
        const int c0 = c8 * 8;
        const int sw = c8 << 2;

        unsigned int w8[8];
        #pragma unroll
        for (int jj = 0; jj < 8; jj++) {
            const int w = (c0 + jj) * 64 + (p2 >> 1);
            w8[jj] = smw[w ^ sw];
        }
        uint4 lo, hi;
        lo.x = __byte_perm(w8[0], w8[1], 0x5410);
        lo.y = __byte_perm(w8[2], w8[3], 0x5410);
        lo.z = __byte_perm(w8[4], w8[5], 0x5410);
        lo.w = __byte_perm(w8[6], w8[7], 0x5410);
        hi.x = __byte_perm(w8[0], w8[1], 0x7632);
        hi.y = __byte_perm(w8[2], w8[3], 0x7632);
        hi.z = __byte_perm(w8[4], w8[5], 0x7632);
        hi.w = __byte_perm(w8[6], w8[7], 0x7632);

        ob[p2 * 8 + c8]       = lo;
        ob[(p2 + 1) * 8 + c8] = hi;
    }
}

// -------------------------------------------------------------------------
// Kernel 2: bilinear grid sample from NHWC fp16 scratch.
// Phase A: threads 0..63 compute byte offsets + half2-packed weights.
// Phase B: 4 pixels per LDG.128 warp instruction (8 lanes x 16B each);
//          HFMA2 blend entirely in fp16 (no converts, no repack).
// Phase C: half2 smem -> float4 coalesced streaming NCHW store.
// -------------------------------------------------------------------------
__global__ __launch_bounds__(256, 5) void grid_sample_kernel(
    const float* __restrict__ grid, float* __restrict__ out) {
    __shared__ int4         soff[64];       // byte offsets of 4 corners
    __shared__ uint4        swq[64];        // 4 weights as half2 (w,w)
    __shared__ unsigned int smq[64 * 33];   // [pixel][chpair] half2 staging

    const int bid     = blockIdx.x;
    const int wo_base = (bid & 3) * 64;
    const int ho      = (bid >> 2) & (HO_ - 1);
    const int n       = bid >> 10;

    const int tid  = threadIdx.x;
    const int warp = tid >> 5;
    const int lane = tid & 31;

    if (tid < 64) {
        const float2* gp =
            (const float2*)(grid + (((size_t)n * HO_ + ho) * WO_ + wo_base) * 2);
        const float2 g = __ldcs(&gp[tid]);

        const float ix = (g.x + 1.0f) * 0.5f * (float)(W_ - 1);
        const float iy = (g.y + 1.0f) * 0.5f * (float)(H_ - 1);

        const float x0f = floorf(ix);
        const float y0f = floorf(iy);
        const float wx1 = ix - x0f;
        const float wy1 = iy - y0f;
        const float wx0 = 1.0f - wx1;
        const float wy0 = 1.0f - wy1;

        const int xi = (int)x0f;
        const int yi = (int)y0f;
        const int x0 = min(max(xi,     0), W_ - 1);
        const int x1 = min(max(xi + 1, 0), W_ - 1);
        const int y0 = min(max(yi,     0), H_ - 1);
        const int y1 = min(max(yi + 1, 0), H_ - 1);

        int4 o;                                   // BYTE offsets (row = 128B)
        o.x = (y0 * W_ + x0) * (C_ * 2);
        o.y = (y0 * W_ + x1) * (C_ * 2);
        o.z = (y1 * W_ + x0) * (C_ * 2);
        o.w = (y1 * W_ + x1) * (C_ * 2);
        soff[tid] = o;

        uint4 wq;
        wq.x = h2_as_u(__float2half2_rn(wy0 * wx0));
        wq.y = h2_as_u(__float2half2_rn(wy0 * wx1));
        wq.z = h2_as_u(__float2half2_rn(wy1 * wx0));
        wq.w = h2_as_u(__float2half2_rn(wy1 * wx1));
        swq[tid] = wq;
    }
    __syncthreads();

    const char* xb = (const char*)(g_xt + (size_t)n * ((size_t)HW_ * C_));
    const int psel = lane >> 3;     // which of 4 pixels this lane serves
    const int sub  = lane & 7;      // 16B chunk within the 128B channel row
    const int sb   = sub * 16;

    #pragma unroll
    for (int g = 0; g < 2; g++) {
        const int p = warp * 8 + g * 4 + psel;
        const int4  o  = soff[p];   // LDS.128 (4 distinct addrs, bcast x8)
        const uint4 wq = swq[p];    // LDS.128

        // One LDG.128 per corner serves 4 pixels (512B across 4x128B rows).
        const uint4 v00 = *(const uint4*)(xb + o.x + sb);
        const uint4 v01 = *(const uint4*)(xb + o.y + sb);
        const uint4 v10 = *(const uint4*)(xb + o.z + sb);
        const uint4 v11 = *(const uint4*)(xb + o.w + sb);

        const __half2 w00 = u_as_h2(wq.x);
        const __half2 w01 = u_as_h2(wq.y);
        const __half2 w10 = u_as_h2(wq.z);
        const __half2 w11 = u_as_h2(wq.w);

        unsigned int r[4];
        {
            __half2 a;
            a = __hmul2(u_as_h2(v00.x), w00);
            a = __hfma2(u_as_h2(v01.x), w01, a);
            a = __hfma2(u_as_h2(v10.x), w10, a);
            a = __hfma2(u_as_h2(v11.x), w11, a);
            r[0] = h2_as_u(a);
            a = __hmul2(u_as_h2(v00.y), w00);
            a = __hfma2(u_as_h2(v01.y), w01, a);
            a = __hfma2(u_as_h2(v10.y), w10, a);
            a = __hfma2(u_as_h2(v11.y), w11, a);
            r[1] = h2_as_u(a);
            a = __hmul2(u_as_h2(v00.z), w00);
            a = __hfma2(u_as_h2(v01.z), w01, a);
            a = __hfma2(u_as_h2(v10.z), w10, a);
            a = __hfma2(u_as_h2(v11.z), w11, a);
            r[2] = h2_as_u(a);
            a = __hmul2(u_as_h2(v00.w), w00);
            a = __hfma2(u_as_h2(v01.w), w01, a);
            a = __hfma2(u_as_h2(v10.w), w10, a);
            a = __hfma2(u_as_h2(v11.w), w11, a);
            r[3] = h2_as_u(a);
        }

        // Conflict-free: the 4 pixel-rows land in disjoint bank residues.
        #pragma unroll
        for (int k = 0; k < 4; k++)
            smq[p * 33 + sub * 4 + k] = r[k];
    }
    __syncthreads();

    // Phase C: NCHW store, float4 per thread per iter, coalesced, streaming.
    float* obase = out + (size_t)n * (C_ * HO_ * WO_) + (size_t)ho * WO_ + wo_base;
    #pragma unroll
    for (int it = 0; it < 4; it++) {
        const int u  = tid + 256 * it;    // 0..1023
        const int c  = u >> 4;            // channel 0..63
        const int q  = u & 15;            // float4 chunk within 64 pixels
        const int cp = c >> 1;
        const int hi = c & 1;

        float4 v;
        {
            const __half2 h0 = u_as_h2(smq[(q * 4 + 0) * 33 + cp]);
            const __half2 h1 = u_as_h2(smq[(q * 4 + 1) * 33 + cp]);
            const __half2 h2 = u_as_h2(smq[(q * 4 + 2) * 33 + cp]);
            const __half2 h3 = u_as_h2(smq[(q * 4 + 3) * 33 + cp]);
            v.x = hi ? __high2float(h0) : __low2float(h0);
            v.y = hi ? __high2float(h1) : __low2float(h1);
            v.z = hi ? __high2float(h2) : __low2float(h2);
            v.w = hi ? __high2float(h3) : __low2float(h3);
        }
        __stcs((float4*)(obase + (size_t)c * (HO_ * WO_) + q * 4), v);
    }
}

extern "C" void kernel_launch(void* const* d_in, const int* in_sizes, int n_in,
                              void* d_out, int out_size) {
    const float* x    = (const float*)d_in[0];   // [N, C, H, W]
    const float* grid = (const float*)d_in[1];   // [N, HO, WO, 2]
    float* out        = (float*)d_out;           // [N, C, HO, WO]
    (void)in_sizes; (void)n_in; (void)out_size;

    // Kernel 1: NCHW fp32 -> NHWC fp16 (streaming reads, wide ops)
    dim3 tgrid(HW_ / 128, N_);      // (512, 8)
    nchw_to_nhwc_h<<<tgrid, 256>>>(x);

    // Kernel 2: gather (L2-resident scratch) + fp16 blend + streaming store
    const int nblocks = N_ * HO_ * (WO_ / 64);   // 8192
    grid_sample_kernel<<<nblocks, 256>>>(grid, out);
}